// round 8
// baseline (speedup 1.0000x reference)
#include <cuda_runtime.h>
#include <cuda_bf16.h>
#include <cstdint>
#include <math.h>

#define B_  4
#define N_  4096
#define C_  1024
#define H_  16
#define D_  64
#define KL_ 256
#define C3_ 3072

// fp32 scratch
__device__ float g_qkv[B_ * N_ * C3_];
__device__ float g_klm[B_ * H_ * KL_ * D_];
__device__ float g_vlm[B_ * H_ * KL_ * D_];
__device__ float g_ao [B_ * H_ * N_ * D_];

// split-precision bf16 scratch (hi/lo)
__device__ __nv_bfloat16 g_xh [B_ * N_ * C_];
__device__ __nv_bfloat16 g_xl [B_ * N_ * C_];
__device__ __nv_bfloat16 g_w3h[C3_ * C_];
__device__ __nv_bfloat16 g_w3l[C3_ * C_];
__device__ __nv_bfloat16 g_aoh[B_ * N_ * C_];
__device__ __nv_bfloat16 g_aol[B_ * N_ * C_];
__device__ __nv_bfloat16 g_wph[C_ * C_];
__device__ __nv_bfloat16 g_wpl[C_ * C_];
// landmark operands
__device__ __nv_bfloat16 g_eh [H_ * KL_ * N_];
__device__ __nv_bfloat16 g_el [H_ * KL_ * N_];
__device__ __nv_bfloat16 g_kth[B_ * H_ * D_ * N_];
__device__ __nv_bfloat16 g_ktl[B_ * H_ * D_ * N_];
__device__ __nv_bfloat16 g_vth[B_ * H_ * D_ * N_];
__device__ __nv_bfloat16 g_vtl[B_ * H_ * D_ * N_];

// ---------------------------------------------------------------------------
// helpers
// ---------------------------------------------------------------------------
__device__ __forceinline__ uint32_t smem_u32(const void* p) {
    uint32_t a;
    asm("{ .reg .u64 t; cvta.to.shared.u64 t, %1; cvt.u32.u64 %0, t; }"
        : "=r"(a) : "l"(p));
    return a;
}
__device__ __forceinline__ void cp16(uint32_t dst, const void* src) {
    asm volatile("cp.async.cg.shared.global [%0], [%1], 16;"
                 :: "r"(dst), "l"(src) : "memory");
}
__device__ __forceinline__ void cp_commit() {
    asm volatile("cp.async.commit_group;" ::: "memory");
}
#define CP_WAIT(n) asm volatile("cp.async.wait_group %0;" :: "n"(n) : "memory")

#define MMA16816(d, a, b) \
    asm volatile( \
        "mma.sync.aligned.m16n8k16.row.col.f32.bf16.bf16.f32 " \
        "{%0,%1,%2,%3}, {%4,%5,%6,%7}, {%8,%9}, {%0,%1,%2,%3};" \
        : "+f"((d)[0]), "+f"((d)[1]), "+f"((d)[2]), "+f"((d)[3]) \
        : "r"((a)[0]), "r"((a)[1]), "r"((a)[2]), "r"((a)[3]), \
          "r"((b)[0]), "r"((b)[1]))

// ---------------------------------------------------------------------------
// split fp32 -> (hi, lo) bf16
// ---------------------------------------------------------------------------
__global__ __launch_bounds__(256)
void split_kernel(const float* __restrict__ in, __nv_bfloat16* __restrict__ hi,
                  __nv_bfloat16* __restrict__ lo, int n4)
{
    int i = blockIdx.x * blockDim.x + threadIdx.x;
    if (i >= n4) return;
    float4 v = ((const float4*)in)[i];
    __nv_bfloat16 h0 = __float2bfloat16(v.x);
    __nv_bfloat16 h1 = __float2bfloat16(v.y);
    __nv_bfloat16 h2 = __float2bfloat16(v.z);
    __nv_bfloat16 h3 = __float2bfloat16(v.w);
    __nv_bfloat16 l0 = __float2bfloat16(v.x - __bfloat162float(h0));
    __nv_bfloat16 l1 = __float2bfloat16(v.y - __bfloat162float(h1));
    __nv_bfloat16 l2 = __float2bfloat16(v.z - __bfloat162float(h2));
    __nv_bfloat16 l3 = __float2bfloat16(v.w - __bfloat162float(h3));
    __nv_bfloat162* hp = (__nv_bfloat162*)hi;
    __nv_bfloat162* lp = (__nv_bfloat162*)lo;
    hp[2 * i]     = __halves2bfloat162(h0, h1);
    hp[2 * i + 1] = __halves2bfloat162(h2, h3);
    lp[2 * i]     = __halves2bfloat162(l0, l1);
    lp[2 * i + 1] = __halves2bfloat162(l2, l3);
}

// ---------------------------------------------------------------------------
// K/V transpose-split
// ---------------------------------------------------------------------------
__global__ __launch_bounds__(256)
void kvsplit_kernel(const float* __restrict__ qkv,
                    __nv_bfloat16* __restrict__ kth, __nv_bfloat16* __restrict__ ktl,
                    __nv_bfloat16* __restrict__ vth, __nv_bfloat16* __restrict__ vtl)
{
    __shared__ float tile[64][68];
    const int bid   = blockIdx.x;
    const int which = bid & 1;
    const int bh    = (bid >> 1) & 63;
    const int nc    = bid >> 7;
    const int b = bh >> 4, h = bh & 15;
    const int tid = threadIdx.x;

    {
        const int r = tid >> 2, cgp = (tid & 3) << 2;
        const float* src = qkv + ((size_t)(b * N_ + nc * 64 + r)) * C3_
                         + (1 + which) * C_ + h * D_;
#pragma unroll
        for (int i = 0; i < 4; i++) {
            float4 v = *(const float4*)(src + (cgp + i) * 4);
            tile[r][(cgp + i) * 4 + 0] = v.x;
            tile[r][(cgp + i) * 4 + 1] = v.y;
            tile[r][(cgp + i) * 4 + 2] = v.z;
            tile[r][(cgp + i) * 4 + 3] = v.w;
        }
    }
    __syncthreads();

    __nv_bfloat16* dh = (which ? vth : kth) + ((size_t)bh * D_) * N_;
    __nv_bfloat16* dl = (which ? vtl : ktl) + ((size_t)bh * D_) * N_;
    const int d = tid >> 2, ns = (tid & 3) * 16;
    __nv_bfloat162 oh[8], ol[8];
#pragma unroll
    for (int i = 0; i < 8; i++) {
        float f0 = tile[ns + 2 * i][d];
        float f1 = tile[ns + 2 * i + 1][d];
        __nv_bfloat16 h0 = __float2bfloat16(f0);
        __nv_bfloat16 h1 = __float2bfloat16(f1);
        __nv_bfloat16 l0 = __float2bfloat16(f0 - __bfloat162float(h0));
        __nv_bfloat16 l1 = __float2bfloat16(f1 - __bfloat162float(h1));
        oh[i] = __halves2bfloat162(h0, h1);
        ol[i] = __halves2bfloat162(l0, l1);
    }
    size_t off = (size_t)d * N_ + nc * 64 + ns;
    *(uint4*)(dh + off)     = *(uint4*)&oh[0];
    *(uint4*)(dh + off + 8) = *(uint4*)&oh[4];
    *(uint4*)(dl + off)     = *(uint4*)&ol[0];
    *(uint4*)(dl + off + 8) = *(uint4*)&ol[4];
}

// ---------------------------------------------------------------------------
// mma.sync split-bf16 GEMM: C[M,Nc] = A[M,1024] @ B[Nc,1024]^T (+bias)
// CTA tile 128x256, 512 threads (16 warps, 4m x 4n), BK=32, 3-stage cp.async.
// ---------------------------------------------------------------------------
#define GK_    1024
#define BKC_   32
#define NCH_   (GK_ / BKC_)       // 32
#define PADK_  40                 // row pitch elems (80 B)
#define GA_B   (128 * PADK_ * 2)  // 10240 B per A matrix
#define GB_B   (256 * PADK_ * 2)  // 20480 B per B matrix
#define GSTG_  (2 * GA_B + 2 * GB_B)  // 61440 B
#define GSMEM  (3 * GSTG_)            // 184320 B

__device__ __forceinline__ void load_stage(
    uint32_t sb, const __nv_bfloat16* __restrict__ Ah, const __nv_bfloat16* __restrict__ Al,
    const __nv_bfloat16* __restrict__ Bh, const __nv_bfloat16* __restrict__ Bl,
    int m0, int n0, int kof, int tid)
{
    if (tid < 256) {
        const int r  = tid >> 1;
        const int hf = tid & 1;
        const uint32_t so = (uint32_t)r * (PADK_ * 2) + hf * 32;
        const size_t gA = (size_t)(m0 + r) * GK_ + kof + hf * 16;
        cp16(sb + so,               Ah + gA);
        cp16(sb + so + 16,          Ah + gA + 8);
        cp16(sb + GA_B + so,        Al + gA);
        cp16(sb + GA_B + so + 16,   Al + gA + 8);
    } else {
        const int r = tid - 256;                       // 0..255 B row
        const uint32_t so = (uint32_t)r * (PADK_ * 2);
        const size_t gB = (size_t)(n0 + r) * GK_ + kof;
        const uint32_t bh_base = sb + 2 * GA_B;
        const uint32_t bl_base = bh_base + GB_B;
#pragma unroll
        for (int j = 0; j < 4; j++) {
            cp16(bh_base + so + j * 16, Bh + gB + j * 8);
            cp16(bl_base + so + j * 16, Bl + gB + j * 8);
        }
    }
}

__global__ __launch_bounds__(512)
void gemm_mma_kernel(const __nv_bfloat16* __restrict__ Ah, const __nv_bfloat16* __restrict__ Al,
                     const __nv_bfloat16* __restrict__ Bh, const __nv_bfloat16* __restrict__ Bl,
                     float* __restrict__ Cm, const float* __restrict__ bias, int Nc)
{
    extern __shared__ __align__(16) char dyn[];
    const uint32_t sbase = smem_u32(dyn);

    const int tid  = threadIdx.x;
    const int warp = tid >> 5, lane = tid & 31;
    const int wm   = warp & 3;        // m offset 32*wm
    const int wn   = warp >> 2;       // n offset 64*wn (0..3)
    const int gid  = lane >> 2;
    const int tig  = lane & 3;
    const int m0 = blockIdx.y * 128;
    const int n0 = blockIdx.x * 256;

    float acc[2][8][4];
#pragma unroll
    for (int mi = 0; mi < 2; mi++)
#pragma unroll
        for (int j = 0; j < 8; j++)
#pragma unroll
            for (int q = 0; q < 4; q++) acc[mi][j][q] = 0.f;

    load_stage(sbase,         Ah, Al, Bh, Bl, m0, n0, 0 * BKC_, tid);
    cp_commit();
    load_stage(sbase + GSTG_, Ah, Al, Bh, Bl, m0, n0, 1 * BKC_, tid);
    cp_commit();

    for (int c = 0; c < NCH_; c++) {
        const int st = c % 3;
        if (c + 2 < NCH_) {
            load_stage(sbase + ((c + 2) % 3) * GSTG_, Ah, Al, Bh, Bl, m0, n0,
                       (c + 2) * BKC_, tid);
            cp_commit();
            CP_WAIT(2);
        } else if (c + 1 < NCH_) {
            CP_WAIT(1);
        } else {
            CP_WAIT(0);
        }
        __syncthreads();

        const char* stg = dyn + st * GSTG_;
        const __nv_bfloat16* sA  = (const __nv_bfloat16*)(stg);
        const __nv_bfloat16* sAl = (const __nv_bfloat16*)(stg + GA_B);
        const __nv_bfloat16* sB  = (const __nv_bfloat16*)(stg + 2 * GA_B);
        const __nv_bfloat16* sBl = (const __nv_bfloat16*)(stg + 2 * GA_B + GB_B);

#pragma unroll
        for (int kk = 0; kk < BKC_; kk += 16) {
            uint32_t rbh[8][2], rbl[8][2];
#pragma unroll
            for (int j = 0; j < 8; j++) {
                const int rb = wn * 64 + j * 8 + gid;
                rbh[j][0] = *(const uint32_t*)&sB [rb * PADK_ + kk + 2 * tig];
                rbh[j][1] = *(const uint32_t*)&sB [rb * PADK_ + kk + 2 * tig + 8];
                rbl[j][0] = *(const uint32_t*)&sBl[rb * PADK_ + kk + 2 * tig];
                rbl[j][1] = *(const uint32_t*)&sBl[rb * PADK_ + kk + 2 * tig + 8];
            }
            uint32_t ra[2][4];
#pragma unroll
            for (int mi = 0; mi < 2; mi++) {
                const int rr = wm * 32 + mi * 16 + gid;
                ra[mi][0] = *(const uint32_t*)&sA[rr * PADK_ + kk + 2 * tig];
                ra[mi][1] = *(const uint32_t*)&sA[(rr + 8) * PADK_ + kk + 2 * tig];
                ra[mi][2] = *(const uint32_t*)&sA[rr * PADK_ + kk + 2 * tig + 8];
                ra[mi][3] = *(const uint32_t*)&sA[(rr + 8) * PADK_ + kk + 2 * tig + 8];
            }
#pragma unroll
            for (int mi = 0; mi < 2; mi++)
#pragma unroll
                for (int j = 0; j < 8; j++) {
                    MMA16816(acc[mi][j], ra[mi], rbh[j]);
                    MMA16816(acc[mi][j], ra[mi], rbl[j]);
                }
#pragma unroll
            for (int mi = 0; mi < 2; mi++) {
                const int rr = wm * 32 + mi * 16 + gid;
                ra[mi][0] = *(const uint32_t*)&sAl[rr * PADK_ + kk + 2 * tig];
                ra[mi][1] = *(const uint32_t*)&sAl[(rr + 8) * PADK_ + kk + 2 * tig];
                ra[mi][2] = *(const uint32_t*)&sAl[rr * PADK_ + kk + 2 * tig + 8];
                ra[mi][3] = *(const uint32_t*)&sAl[(rr + 8) * PADK_ + kk + 2 * tig + 8];
            }
#pragma unroll
            for (int mi = 0; mi < 2; mi++)
#pragma unroll
                for (int j = 0; j < 8; j++)
                    MMA16816(acc[mi][j], ra[mi], rbh[j]);
        }
        __syncthreads();
    }

#pragma unroll
    for (int mi = 0; mi < 2; mi++) {
        const int row = m0 + wm * 32 + mi * 16 + gid;
#pragma unroll
        for (int j = 0; j < 8; j++) {
            const int col = n0 + wn * 64 + j * 8 + 2 * tig;
            float b0 = 0.f, b1 = 0.f;
            if (bias) { b0 = __ldg(bias + col); b1 = __ldg(bias + col + 1); }
            float2 s0 = make_float2(acc[mi][j][0] + b0, acc[mi][j][1] + b1);
            float2 s1 = make_float2(acc[mi][j][2] + b0, acc[mi][j][3] + b1);
            *(float2*)(Cm + (size_t)row * Nc + col)       = s0;
            *(float2*)(Cm + (size_t)(row + 8) * Nc + col) = s1;
        }
    }
}

// ---------------------------------------------------------------------------
// Landmark MMA
// ---------------------------------------------------------------------------
#define LK_    4096
#define LBK_   32
#define LPAD_  40
#define LA_B   (256 * LPAD_ * 2)
#define LB_B   (64 * LPAD_ * 2)
#define LSTG_  (2 * LA_B + 2 * LB_B)
#define LSMEM  (2 * LSTG_)

__device__ __forceinline__ void lm_load_stage(
    uint32_t sb, const __nv_bfloat16* __restrict__ Ah, const __nv_bfloat16* __restrict__ Al,
    const __nv_bfloat16* __restrict__ Bh, const __nv_bfloat16* __restrict__ Bl,
    int kof, int tid)
{
    {
        const size_t g = (size_t)tid * LK_ + kof;
        const uint32_t so = (uint32_t)tid * (LPAD_ * 2);
#pragma unroll
        for (int j = 0; j < 4; j++) {
            cp16(sb + so + j * 16,        Ah + g + j * 8);
            cp16(sb + LA_B + so + j * 16, Al + g + j * 8);
        }
    }
    {
        const int t = tid & 127;
        const int r = t >> 1, hf = t & 1;
        const size_t g = (size_t)r * LK_ + kof + hf * 16;
        const uint32_t so = (uint32_t)r * (LPAD_ * 2) + hf * 32;
        const uint32_t base = sb + 2 * LA_B + (tid >> 7) * LB_B;
        const __nv_bfloat16* src = (tid < 128) ? Bh : Bl;
        cp16(base + so,      src + g);
        cp16(base + so + 16, src + g + 8);
    }
}

__global__ __launch_bounds__(256)
void landmark_mma_kernel(const __nv_bfloat16* __restrict__ Eh, const __nv_bfloat16* __restrict__ El,
                         const __nv_bfloat16* __restrict__ kth, const __nv_bfloat16* __restrict__ ktl,
                         const __nv_bfloat16* __restrict__ vth, const __nv_bfloat16* __restrict__ vtl,
                         float* __restrict__ klm, float* __restrict__ vlm)
{
    extern __shared__ __align__(16) char dyn[];
    const uint32_t sbase = smem_u32(dyn);

    const int bid   = blockIdx.x;
    const int which = bid & 1;
    const int bh    = bid >> 1;
    const int h     = bh & 15;

    const __nv_bfloat16* Ah = Eh + (size_t)h * KL_ * LK_;
    const __nv_bfloat16* Al = El + (size_t)h * KL_ * LK_;
    const __nv_bfloat16* Bh = (which ? vth : kth) + (size_t)bh * D_ * LK_;
    const __nv_bfloat16* Bl = (which ? vtl : ktl) + (size_t)bh * D_ * LK_;
    float* outp = (which ? vlm : klm) + (size_t)bh * KL_ * D_;

    const int tid  = threadIdx.x;
    const int warp = tid >> 5, lane = tid & 31;
    const int wm   = warp & 3;
    const int wn   = warp >> 2;
    const int gid  = lane >> 2;
    const int tig  = lane & 3;

    float acc[4][4][4];
#pragma unroll
    for (int mi = 0; mi < 4; mi++)
#pragma unroll
        for (int j = 0; j < 4; j++)
#pragma unroll
            for (int q = 0; q < 4; q++) acc[mi][j][q] = 0.f;

    lm_load_stage(sbase, Ah, Al, Bh, Bl, 0, tid);
    cp_commit();

    for (int c = 0; c < LK_ / LBK_; c++) {
        const int st = c & 1;
        if (c + 1 < LK_ / LBK_) {
            lm_load_stage(sbase + (st ^ 1) * LSTG_, Ah, Al, Bh, Bl,
                          (c + 1) * LBK_, tid);
            cp_commit();
            CP_WAIT(1);
        } else {
            CP_WAIT(0);
        }
        __syncthreads();

        const __nv_bfloat16* sA  = (const __nv_bfloat16*)(dyn + st * LSTG_);
        const __nv_bfloat16* sAl = (const __nv_bfloat16*)(dyn + st * LSTG_ + LA_B);
        const __nv_bfloat16* sB  = (const __nv_bfloat16*)(dyn + st * LSTG_ + 2 * LA_B);
        const __nv_bfloat16* sBl = (const __nv_bfloat16*)(dyn + st * LSTG_ + 2 * LA_B + LB_B);

#pragma unroll
        for (int kk = 0; kk < LBK_; kk += 16) {
            uint32_t rbh[4][2], rbl[4][2];
#pragma unroll
            for (int j = 0; j < 4; j++) {
                const int rb = wn * 32 + j * 8 + gid;
                rbh[j][0] = *(const uint32_t*)&sB [rb * LPAD_ + kk + 2 * tig];
                rbh[j][1] = *(const uint32_t*)&sB [rb * LPAD_ + kk + 2 * tig + 8];
                rbl[j][0] = *(const uint32_t*)&sBl[rb * LPAD_ + kk + 2 * tig];
                rbl[j][1] = *(const uint32_t*)&sBl[rb * LPAD_ + kk + 2 * tig + 8];
            }
            uint32_t ra[4][4];
#pragma unroll
            for (int mi = 0; mi < 4; mi++) {
                const int rr = wm * 64 + mi * 16 + gid;
                ra[mi][0] = *(const uint32_t*)&sA[rr * LPAD_ + kk + 2 * tig];
                ra[mi][1] = *(const uint32_t*)&sA[(rr + 8) * LPAD_ + kk + 2 * tig];
                ra[mi][2] = *(const uint32_t*)&sA[rr * LPAD_ + kk + 2 * tig + 8];
                ra[mi][3] = *(const uint32_t*)&sA[(rr + 8) * LPAD_ + kk + 2 * tig + 8];
            }
#pragma unroll
            for (int mi = 0; mi < 4; mi++)
#pragma unroll
                for (int j = 0; j < 4; j++)
                    MMA16816(acc[mi][j], ra[mi], rbh[j]);
#pragma unroll
            for (int mi = 0; mi < 4; mi++)
#pragma unroll
                for (int j = 0; j < 4; j++)
                    MMA16816(acc[mi][j], ra[mi], rbl[j]);
#pragma unroll
            for (int mi = 0; mi < 4; mi++) {
                const int rr = wm * 64 + mi * 16 + gid;
                ra[mi][0] = *(const uint32_t*)&sAl[rr * LPAD_ + kk + 2 * tig];
                ra[mi][1] = *(const uint32_t*)&sAl[(rr + 8) * LPAD_ + kk + 2 * tig];
                ra[mi][2] = *(const uint32_t*)&sAl[rr * LPAD_ + kk + 2 * tig + 8];
                ra[mi][3] = *(const uint32_t*)&sAl[(rr + 8) * LPAD_ + kk + 2 * tig + 8];
            }
#pragma unroll
            for (int mi = 0; mi < 4; mi++)
#pragma unroll
                for (int j = 0; j < 4; j++)
                    MMA16816(acc[mi][j], ra[mi], rbh[j]);
        }
        __syncthreads();
    }

#pragma unroll
    for (int mi = 0; mi < 4; mi++) {
        const int row = wm * 64 + mi * 16 + gid;
#pragma unroll
        for (int j = 0; j < 4; j++) {
            const int col = wn * 32 + j * 8 + 2 * tig;
            *(float2*)(outp + (size_t)row * D_ + col) =
                make_float2(acc[mi][j][0], acc[mi][j][1]);
            *(float2*)(outp + (size_t)(row + 8) * D_ + col) =
                make_float2(acc[mi][j][2], acc[mi][j][3]);
        }
    }
}

// ---------------------------------------------------------------------------
// Fused attention (SIMT, unchanged)
// ---------------------------------------------------------------------------
#define SP_ 264
#define ATTN_SMEM_FLOATS (16384 + 16384 + 2048 + 32 * SP_ + 32)
#define ATTN_SMEM_BYTES  (ATTN_SMEM_FLOATS * 4)

__global__ __launch_bounds__(256)
void attn_kernel(const float* __restrict__ qkv, const float* __restrict__ klm,
                 const float* __restrict__ vlm_g, float* __restrict__ ao)
{
    extern __shared__ float sm[];
    float* klmT = sm;
    float* vlm  = sm + 16384;
    float* qT   = sm + 32768;
    float* sS   = sm + 34816;
    float* rec  = sm + 34816 + 32 * SP_;

    const int bh = blockIdx.x;
    const int b = bh >> 4, h = bh & 15;
    const int tid = threadIdx.x;

    {
        const float* src = klm + (bh * KL_ + tid) * D_;
#pragma unroll
        for (int j = 0; j < 16; j++) {
            float4 v = *(const float4*)(src + j * 4);
            klmT[(j * 4 + 0) * KL_ + tid] = v.x;
            klmT[(j * 4 + 1) * KL_ + tid] = v.y;
            klmT[(j * 4 + 2) * KL_ + tid] = v.z;
            klmT[(j * 4 + 3) * KL_ + tid] = v.w;
        }
        const float4* vsrc = (const float4*)(vlm_g + bh * KL_ * D_);
        float4* vdst = (float4*)vlm;
#pragma unroll
        for (int j = 0; j < 16; j++) vdst[j * 256 + tid] = vsrc[j * 256 + tid];
    }

    const int rg  = (tid >> 5) << 2;
    const int cg  = (tid & 31) << 3;
    const int cg2 = (tid & 31) << 1;
    const int w = tid >> 5, lane = tid & 31;
    const int nb = blockIdx.y * 128;

    for (int t0 = nb; t0 < nb + 128; t0 += 32) {
        {
            const int r = tid & 31, seg = (tid >> 5) << 3;
            const float* qsrc = qkv + (size_t)(b * N_ + t0 + r) * C3_ + h * D_ + seg;
            float4 v0 = *(const float4*)(qsrc);
            float4 v1 = *(const float4*)(qsrc + 4);
            qT[(seg + 0) * 32 + r] = v0.x * 0.125f;
            qT[(seg + 1) * 32 + r] = v0.y * 0.125f;
            qT[(seg + 2) * 32 + r] = v0.z * 0.125f;
            qT[(seg + 3) * 32 + r] = v0.w * 0.125f;
            qT[(seg + 4) * 32 + r] = v1.x * 0.125f;
            qT[(seg + 5) * 32 + r] = v1.y * 0.125f;
            qT[(seg + 6) * 32 + r] = v1.z * 0.125f;
            qT[(seg + 7) * 32 + r] = v1.w * 0.125f;
        }
        __syncthreads();

        float a1[4][8];
#pragma unroll
        for (int i = 0; i < 4; i++)
#pragma unroll
            for (int j = 0; j < 8; j++) a1[i][j] = 0.f;

#pragma unroll 4
        for (int d = 0; d < 64; d++) {
            float4 qv = *(const float4*)&qT[d * 32 + rg];
            float4 k0 = *(const float4*)&klmT[d * KL_ + cg];
            float4 k1 = *(const float4*)&klmT[d * KL_ + cg + 4];
            float qa[4] = {qv.x, qv.y, qv.z, qv.w};
            float kb[8] = {k0.x, k0.y, k0.z, k0.w, k1.x, k1.y, k1.z, k1.w};
#pragma unroll
            for (int i = 0; i < 4; i++)
#pragma unroll
                for (int j = 0; j < 8; j++)
                    a1[i][j] += qa[i] * kb[j];
        }
#pragma unroll
        for (int i = 0; i < 4; i++) {
            *(float4*)&sS[(rg + i) * SP_ + cg] =
                make_float4(a1[i][0], a1[i][1], a1[i][2], a1[i][3]);
            *(float4*)&sS[(rg + i) * SP_ + cg + 4] =
                make_float4(a1[i][4], a1[i][5], a1[i][6], a1[i][7]);
        }
        __syncthreads();

#pragma unroll
        for (int i = 0; i < 4; i++) {
            const int r = w * 4 + i;
            float* row = &sS[r * SP_];
            float v[8];
#pragma unroll
            for (int j = 0; j < 8; j++) v[j] = row[lane + 32 * j];
            float m = v[0];
#pragma unroll
            for (int j = 1; j < 8; j++) m = fmaxf(m, v[j]);
#pragma unroll
            for (int off = 16; off > 0; off >>= 1)
                m = fmaxf(m, __shfl_xor_sync(0xffffffffu, m, off));
            float s = 0.f;
#pragma unroll
            for (int j = 0; j < 8; j++) { v[j] = __expf(v[j] - m); s += v[j]; }
#pragma unroll
            for (int off = 16; off > 0; off >>= 1)
                s += __shfl_xor_sync(0xffffffffu, s, off);
#pragma unroll
            for (int j = 0; j < 8; j++) row[lane + 32 * j] = v[j];
            if (lane == 0) rec[r] = 1.f / s;
        }
        __syncthreads();

        float a2[4][2];
#pragma unroll
        for (int i = 0; i < 4; i++) { a2[i][0] = 0.f; a2[i][1] = 0.f; }

#pragma unroll 2
        for (int k = 0; k < KL_; k += 4) {
            float4 av0 = *(const float4*)&sS[(rg + 0) * SP_ + k];
            float4 av1 = *(const float4*)&sS[(rg + 1) * SP_ + k];
            float4 av2 = *(const float4*)&sS[(rg + 2) * SP_ + k];
            float4 av3 = *(const float4*)&sS[(rg + 3) * SP_ + k];
            float am[4][4] = {{av0.x, av0.y, av0.z, av0.w},
                              {av1.x, av1.y, av1.z, av1.w},
                              {av2.x, av2.y, av2.z, av2.w},
                              {av3.x, av3.y, av3.z, av3.w}};
#pragma unroll
            for (int kk = 0; kk < 4; kk++) {
                float2 vv = *(const float2*)&vlm[(k + kk) * D_ + cg2];
#pragma unroll
                for (int i = 0; i < 4; i++) {
                    a2[i][0] += am[i][kk] * vv.x;
                    a2[i][1] += am[i][kk] * vv.y;
                }
            }
        }

        float* outp = ao + (size_t)(bh * N_ + t0 + rg) * D_ + cg2;
#pragma unroll
        for (int i = 0; i < 4; i++) {
            float rc = rec[rg + i];
            float2 st = make_float2(a2[i][0] * rc, a2[i][1] * rc);
            *(float2*)(outp + i * D_) = st;
        }
        __syncthreads();
    }
}

// ---------------------------------------------------------------------------
extern "C" void kernel_launch(void* const* d_in, const int* in_sizes, int n_in,
                              void* d_out, int out_size)
{
    (void)in_sizes; (void)n_in; (void)out_size;
    const float* x     = (const float*)d_in[0];
    const float* Wqkv  = (const float*)d_in[1];
    const float* E     = (const float*)d_in[2];
    const float* Wproj = (const float*)d_in[3];
    const float* bproj = (const float*)d_in[4];
    float* out = (float*)d_out;

    void *p_qkv, *p_klm, *p_vlm, *p_ao;
    void *p_xh, *p_xl, *p_w3h, *p_w3l, *p_aoh, *p_aol, *p_wph, *p_wpl;
    void *p_eh, *p_el, *p_kth, *p_ktl, *p_vth, *p_vtl;
    cudaGetSymbolAddress(&p_qkv, g_qkv);
    cudaGetSymbolAddress(&p_klm, g_klm);
    cudaGetSymbolAddress(&p_vlm, g_vlm);
    cudaGetSymbolAddress(&p_ao,  g_ao);
    cudaGetSymbolAddress(&p_xh,  g_xh);
    cudaGetSymbolAddress(&p_xl,  g_xl);
    cudaGetSymbolAddress(&p_w3h, g_w3h);
    cudaGetSymbolAddress(&p_w3l, g_w3l);
    cudaGetSymbolAddress(&p_aoh, g_aoh);
    cudaGetSymbolAddress(&p_aol, g_aol);
    cudaGetSymbolAddress(&p_wph, g_wph);
    cudaGetSymbolAddress(&p_wpl, g_wpl);
    cudaGetSymbolAddress(&p_eh,  g_eh);
    cudaGetSymbolAddress(&p_el,  g_el);
    cudaGetSymbolAddress(&p_kth, g_kth);
    cudaGetSymbolAddress(&p_ktl, g_ktl);
    cudaGetSymbolAddress(&p_vth, g_vth);
    cudaGetSymbolAddress(&p_vtl, g_vtl);

    float* qkv = (float*)p_qkv;
    float* klm = (float*)p_klm;
    float* vlm = (float*)p_vlm;
    float* ao  = (float*)p_ao;

    cudaFuncSetAttribute(attn_kernel, cudaFuncAttributeMaxDynamicSharedMemorySize,
                         ATTN_SMEM_BYTES);
    cudaFuncSetAttribute(gemm_mma_kernel, cudaFuncAttributeMaxDynamicSharedMemorySize,
                         GSMEM);
    cudaFuncSetAttribute(landmark_mma_kernel, cudaFuncAttributeMaxDynamicSharedMemorySize,
                         LSMEM);

    const int XN  = B_ * N_ * C_;
    const int W3N = C3_ * C_;
    const int WPN = C_ * C_;
    const int EN  = H_ * KL_ * N_;

    split_kernel<<<(XN / 4 + 255) / 256, 256>>>(x, (__nv_bfloat16*)p_xh,
                                                (__nv_bfloat16*)p_xl, XN / 4);
    split_kernel<<<(W3N / 4 + 255) / 256, 256>>>(Wqkv, (__nv_bfloat16*)p_w3h,
                                                 (__nv_bfloat16*)p_w3l, W3N / 4);
    split_kernel<<<(EN / 4 + 255) / 256, 256>>>(E, (__nv_bfloat16*)p_eh,
                                                (__nv_bfloat16*)p_el, EN / 4);

    // 1) qkv = x @ Wqkv^T
    gemm_mma_kernel<<<dim3(C3_ / 256, (B_ * N_) / 128), 512, GSMEM>>>(
        (__nv_bfloat16*)p_xh, (__nv_bfloat16*)p_xl,
        (__nv_bfloat16*)p_w3h, (__nv_bfloat16*)p_w3l, qkv, nullptr, C3_);

    // 2) K/V transpose-split
    kvsplit_kernel<<<64 * 64 * 2, 256>>>(qkv,
        (__nv_bfloat16*)p_kth, (__nv_bfloat16*)p_ktl,
        (__nv_bfloat16*)p_vth, (__nv_bfloat16*)p_vtl);

    // 3) landmark projections via MMA
    landmark_mma_kernel<<<128, 256, LSMEM>>>(
        (__nv_bfloat16*)p_eh, (__nv_bfloat16*)p_el,
        (__nv_bfloat16*)p_kth, (__nv_bfloat16*)p_ktl,
        (__nv_bfloat16*)p_vth, (__nv_bfloat16*)p_vtl, klm, vlm);

    // 4) fused attention
    attn_kernel<<<dim3(B_ * H_, 32), 256, ATTN_SMEM_BYTES>>>(qkv, klm, vlm, ao);

    split_kernel<<<(XN / 4 + 255) / 256, 256>>>(ao, (__nv_bfloat16*)p_aoh,
                                                (__nv_bfloat16*)p_aol, XN / 4);
    split_kernel<<<(WPN / 4 + 255) / 256, 256>>>(Wproj, (__nv_bfloat16*)p_wph,
                                                 (__nv_bfloat16*)p_wpl, WPN / 4);

    // 5) out = ao @ Wproj^T + bproj
    gemm_mma_kernel<<<dim3(C_ / 256, (B_ * N_) / 128), 512, GSMEM>>>(
        (__nv_bfloat16*)p_aoh, (__nv_bfloat16*)p_aol,
        (__nv_bfloat16*)p_wph, (__nv_bfloat16*)p_wpl, out, bproj, C_);
}

// round 9
// speedup vs baseline: 1.3531x; 1.3531x over previous
#include <cuda_runtime.h>
#include <cuda_bf16.h>
#include <cstdint>
#include <math.h>

#define B_  4
#define N_  4096
#define C_  1024
#define H_  16
#define D_  64
#define KL_ 256
#define C3_ 3072

// fp32 scratch
__device__ float g_qkv[B_ * N_ * C3_];
__device__ float g_klm[B_ * H_ * KL_ * D_];
__device__ float g_vlm[B_ * H_ * KL_ * D_];
__device__ float g_ao [B_ * H_ * N_ * D_];

// split-precision bf16 scratch (hi/lo)
__device__ __nv_bfloat16 g_xh [B_ * N_ * C_];
__device__ __nv_bfloat16 g_xl [B_ * N_ * C_];
__device__ __nv_bfloat16 g_w3h[C3_ * C_];
__device__ __nv_bfloat16 g_w3l[C3_ * C_];
__device__ __nv_bfloat16 g_aoh[B_ * N_ * C_];
__device__ __nv_bfloat16 g_aol[B_ * N_ * C_];
__device__ __nv_bfloat16 g_wph[C_ * C_];
__device__ __nv_bfloat16 g_wpl[C_ * C_];
// landmark operands
__device__ __nv_bfloat16 g_eh [H_ * KL_ * N_];
__device__ __nv_bfloat16 g_el [H_ * KL_ * N_];
__device__ __nv_bfloat16 g_kth[B_ * H_ * D_ * N_];
__device__ __nv_bfloat16 g_ktl[B_ * H_ * D_ * N_];
__device__ __nv_bfloat16 g_vth[B_ * H_ * D_ * N_];
__device__ __nv_bfloat16 g_vtl[B_ * H_ * D_ * N_];

// ---------------------------------------------------------------------------
// helpers
// ---------------------------------------------------------------------------
__device__ __forceinline__ uint32_t smem_u32(const void* p) {
    uint32_t a;
    asm("{ .reg .u64 t; cvta.to.shared.u64 t, %1; cvt.u32.u64 %0, t; }"
        : "=r"(a) : "l"(p));
    return a;
}
__device__ __forceinline__ void cp16(uint32_t dst, const void* src) {
    asm volatile("cp.async.cg.shared.global [%0], [%1], 16;"
                 :: "r"(dst), "l"(src) : "memory");
}
__device__ __forceinline__ void cp_commit() {
    asm volatile("cp.async.commit_group;" ::: "memory");
}
#define CP_WAIT(n) asm volatile("cp.async.wait_group %0;" :: "n"(n) : "memory")

#define MMA16816(d, a, b) \
    asm volatile( \
        "mma.sync.aligned.m16n8k16.row.col.f32.bf16.bf16.f32 " \
        "{%0,%1,%2,%3}, {%4,%5,%6,%7}, {%8,%9}, {%0,%1,%2,%3};" \
        : "+f"((d)[0]), "+f"((d)[1]), "+f"((d)[2]), "+f"((d)[3]) \
        : "r"((a)[0]), "r"((a)[1]), "r"((a)[2]), "r"((a)[3]), \
          "r"((b)[0]), "r"((b)[1]))

// ---------------------------------------------------------------------------
// split fp32 -> (hi, lo) bf16
// ---------------------------------------------------------------------------
__global__ __launch_bounds__(256)
void split_kernel(const float* __restrict__ in, __nv_bfloat16* __restrict__ hi,
                  __nv_bfloat16* __restrict__ lo, int n4)
{
    int i = blockIdx.x * blockDim.x + threadIdx.x;
    if (i >= n4) return;
    float4 v = ((const float4*)in)[i];
    __nv_bfloat16 h0 = __float2bfloat16(v.x);
    __nv_bfloat16 h1 = __float2bfloat16(v.y);
    __nv_bfloat16 h2 = __float2bfloat16(v.z);
    __nv_bfloat16 h3 = __float2bfloat16(v.w);
    __nv_bfloat16 l0 = __float2bfloat16(v.x - __bfloat162float(h0));
    __nv_bfloat16 l1 = __float2bfloat16(v.y - __bfloat162float(h1));
    __nv_bfloat16 l2 = __float2bfloat16(v.z - __bfloat162float(h2));
    __nv_bfloat16 l3 = __float2bfloat16(v.w - __bfloat162float(h3));
    __nv_bfloat162* hp = (__nv_bfloat162*)hi;
    __nv_bfloat162* lp = (__nv_bfloat162*)lo;
    hp[2 * i]     = __halves2bfloat162(h0, h1);
    hp[2 * i + 1] = __halves2bfloat162(h2, h3);
    lp[2 * i]     = __halves2bfloat162(l0, l1);
    lp[2 * i + 1] = __halves2bfloat162(l2, l3);
}

// ---------------------------------------------------------------------------
// K/V transpose-split
// ---------------------------------------------------------------------------
__global__ __launch_bounds__(256)
void kvsplit_kernel(const float* __restrict__ qkv,
                    __nv_bfloat16* __restrict__ kth, __nv_bfloat16* __restrict__ ktl,
                    __nv_bfloat16* __restrict__ vth, __nv_bfloat16* __restrict__ vtl)
{
    __shared__ float tile[64][68];
    const int bid   = blockIdx.x;
    const int which = bid & 1;
    const int bh    = (bid >> 1) & 63;
    const int nc    = bid >> 7;
    const int b = bh >> 4, h = bh & 15;
    const int tid = threadIdx.x;

    {
        const int r = tid >> 2, cgp = (tid & 3) << 2;
        const float* src = qkv + ((size_t)(b * N_ + nc * 64 + r)) * C3_
                         + (1 + which) * C_ + h * D_;
#pragma unroll
        for (int i = 0; i < 4; i++) {
            float4 v = *(const float4*)(src + (cgp + i) * 4);
            tile[r][(cgp + i) * 4 + 0] = v.x;
            tile[r][(cgp + i) * 4 + 1] = v.y;
            tile[r][(cgp + i) * 4 + 2] = v.z;
            tile[r][(cgp + i) * 4 + 3] = v.w;
        }
    }
    __syncthreads();

    __nv_bfloat16* dh = (which ? vth : kth) + ((size_t)bh * D_) * N_;
    __nv_bfloat16* dl = (which ? vtl : ktl) + ((size_t)bh * D_) * N_;
    const int d = tid >> 2, ns = (tid & 3) * 16;
    __nv_bfloat162 oh[8], ol[8];
#pragma unroll
    for (int i = 0; i < 8; i++) {
        float f0 = tile[ns + 2 * i][d];
        float f1 = tile[ns + 2 * i + 1][d];
        __nv_bfloat16 h0 = __float2bfloat16(f0);
        __nv_bfloat16 h1 = __float2bfloat16(f1);
        __nv_bfloat16 l0 = __float2bfloat16(f0 - __bfloat162float(h0));
        __nv_bfloat16 l1 = __float2bfloat16(f1 - __bfloat162float(h1));
        oh[i] = __halves2bfloat162(h0, h1);
        ol[i] = __halves2bfloat162(l0, l1);
    }
    size_t off = (size_t)d * N_ + nc * 64 + ns;
    *(uint4*)(dh + off)     = *(uint4*)&oh[0];
    *(uint4*)(dh + off + 8) = *(uint4*)&oh[4];
    *(uint4*)(dl + off)     = *(uint4*)&ol[0];
    *(uint4*)(dl + off + 8) = *(uint4*)&ol[4];
}

// ---------------------------------------------------------------------------
// mma.sync split-bf16 GEMM (reverted to R5 config: 128x128, 256 thr, 2-stage)
// ---------------------------------------------------------------------------
#define GK_    1024
#define BKC_   32
#define NCH_   (GK_ / BKC_)
#define PADK_  40
#define TILEB_ (128 * PADK_ * 2)
#define STGB_  (4 * TILEB_)
#define GSMEM  (2 * STGB_)

__device__ __forceinline__ void load_stage(
    uint32_t sb, const __nv_bfloat16* __restrict__ Ah, const __nv_bfloat16* __restrict__ Al,
    const __nv_bfloat16* __restrict__ Bh, const __nv_bfloat16* __restrict__ Bl,
    int m0, int n0, int kof, int tid)
{
    const int r  = tid >> 1;
    const int hf = tid & 1;
    const uint32_t so = (uint32_t)r * (PADK_ * 2) + hf * 32;
    const size_t gA = (size_t)(m0 + r) * GK_ + kof + hf * 16;
    const size_t gB = (size_t)(n0 + r) * GK_ + kof + hf * 16;
    cp16(sb + 0 * TILEB_ + so,      Ah + gA);
    cp16(sb + 0 * TILEB_ + so + 16, Ah + gA + 8);
    cp16(sb + 1 * TILEB_ + so,      Al + gA);
    cp16(sb + 1 * TILEB_ + so + 16, Al + gA + 8);
    cp16(sb + 2 * TILEB_ + so,      Bh + gB);
    cp16(sb + 2 * TILEB_ + so + 16, Bh + gB + 8);
    cp16(sb + 3 * TILEB_ + so,      Bl + gB);
    cp16(sb + 3 * TILEB_ + so + 16, Bl + gB + 8);
}

__global__ __launch_bounds__(256)
void gemm_mma_kernel(const __nv_bfloat16* __restrict__ Ah, const __nv_bfloat16* __restrict__ Al,
                     const __nv_bfloat16* __restrict__ Bh, const __nv_bfloat16* __restrict__ Bl,
                     float* __restrict__ Cm, const float* __restrict__ bias, int Nc)
{
    extern __shared__ __align__(16) char dyn[];
    const uint32_t sbase = smem_u32(dyn);

    const int tid  = threadIdx.x;
    const int warp = tid >> 5, lane = tid & 31;
    const int wm   = warp & 3;
    const int wn   = warp >> 2;
    const int gid  = lane >> 2;
    const int tig  = lane & 3;
    const int m0 = blockIdx.y * 128;
    const int n0 = blockIdx.x * 128;

    float acc[2][8][4];
#pragma unroll
    for (int mi = 0; mi < 2; mi++)
#pragma unroll
        for (int j = 0; j < 8; j++)
#pragma unroll
            for (int q = 0; q < 4; q++) acc[mi][j][q] = 0.f;

    load_stage(sbase, Ah, Al, Bh, Bl, m0, n0, 0, tid);
    cp_commit();

    for (int c = 0; c < NCH_; c++) {
        const int st = c & 1;
        if (c + 1 < NCH_) {
            load_stage(sbase + (st ^ 1) * STGB_, Ah, Al, Bh, Bl, m0, n0,
                       (c + 1) * BKC_, tid);
            cp_commit();
            CP_WAIT(1);
        } else {
            CP_WAIT(0);
        }
        __syncthreads();

        const __nv_bfloat16* sA  = (const __nv_bfloat16*)(dyn + st * STGB_);
        const __nv_bfloat16* sAl = (const __nv_bfloat16*)(dyn + st * STGB_ + TILEB_);
        const __nv_bfloat16* sB  = (const __nv_bfloat16*)(dyn + st * STGB_ + 2 * TILEB_);
        const __nv_bfloat16* sBl = (const __nv_bfloat16*)(dyn + st * STGB_ + 3 * TILEB_);

#pragma unroll
        for (int kk = 0; kk < BKC_; kk += 16) {
            uint32_t rbh[8][2], rbl[8][2];
#pragma unroll
            for (int j = 0; j < 8; j++) {
                const int rb = wn * 64 + j * 8 + gid;
                rbh[j][0] = *(const uint32_t*)&sB [rb * PADK_ + kk + 2 * tig];
                rbh[j][1] = *(const uint32_t*)&sB [rb * PADK_ + kk + 2 * tig + 8];
                rbl[j][0] = *(const uint32_t*)&sBl[rb * PADK_ + kk + 2 * tig];
                rbl[j][1] = *(const uint32_t*)&sBl[rb * PADK_ + kk + 2 * tig + 8];
            }
            uint32_t ra[2][4];
#pragma unroll
            for (int mi = 0; mi < 2; mi++) {
                const int rr = wm * 32 + mi * 16 + gid;
                ra[mi][0] = *(const uint32_t*)&sA[rr * PADK_ + kk + 2 * tig];
                ra[mi][1] = *(const uint32_t*)&sA[(rr + 8) * PADK_ + kk + 2 * tig];
                ra[mi][2] = *(const uint32_t*)&sA[rr * PADK_ + kk + 2 * tig + 8];
                ra[mi][3] = *(const uint32_t*)&sA[(rr + 8) * PADK_ + kk + 2 * tig + 8];
            }
#pragma unroll
            for (int mi = 0; mi < 2; mi++)
#pragma unroll
                for (int j = 0; j < 8; j++) {
                    MMA16816(acc[mi][j], ra[mi], rbh[j]);
                    MMA16816(acc[mi][j], ra[mi], rbl[j]);
                }
#pragma unroll
            for (int mi = 0; mi < 2; mi++) {
                const int rr = wm * 32 + mi * 16 + gid;
                ra[mi][0] = *(const uint32_t*)&sAl[rr * PADK_ + kk + 2 * tig];
                ra[mi][1] = *(const uint32_t*)&sAl[(rr + 8) * PADK_ + kk + 2 * tig];
                ra[mi][2] = *(const uint32_t*)&sAl[rr * PADK_ + kk + 2 * tig + 8];
                ra[mi][3] = *(const uint32_t*)&sAl[(rr + 8) * PADK_ + kk + 2 * tig + 8];
            }
#pragma unroll
            for (int mi = 0; mi < 2; mi++)
#pragma unroll
                for (int j = 0; j < 8; j++)
                    MMA16816(acc[mi][j], ra[mi], rbh[j]);
        }
        __syncthreads();
    }

#pragma unroll
    for (int mi = 0; mi < 2; mi++) {
        const int row = m0 + wm * 32 + mi * 16 + gid;
#pragma unroll
        for (int j = 0; j < 8; j++) {
            const int col = n0 + wn * 64 + j * 8 + 2 * tig;
            float b0 = 0.f, b1 = 0.f;
            if (bias) { b0 = __ldg(bias + col); b1 = __ldg(bias + col + 1); }
            float2 s0 = make_float2(acc[mi][j][0] + b0, acc[mi][j][1] + b1);
            float2 s1 = make_float2(acc[mi][j][2] + b0, acc[mi][j][3] + b1);
            *(float2*)(Cm + (size_t)row * Nc + col)       = s0;
            *(float2*)(Cm + (size_t)(row + 8) * Nc + col) = s1;
        }
    }
}

// ---------------------------------------------------------------------------
// Landmark MMA (unchanged)
// ---------------------------------------------------------------------------
#define LK_    4096
#define LBK_   32
#define LPAD_  40
#define LA_B   (256 * LPAD_ * 2)
#define LB_B   (64 * LPAD_ * 2)
#define LSTG_  (2 * LA_B + 2 * LB_B)
#define LSMEM  (2 * LSTG_)

__device__ __forceinline__ void lm_load_stage(
    uint32_t sb, const __nv_bfloat16* __restrict__ Ah, const __nv_bfloat16* __restrict__ Al,
    const __nv_bfloat16* __restrict__ Bh, const __nv_bfloat16* __restrict__ Bl,
    int kof, int tid)
{
    {
        const size_t g = (size_t)tid * LK_ + kof;
        const uint32_t so = (uint32_t)tid * (LPAD_ * 2);
#pragma unroll
        for (int j = 0; j < 4; j++) {
            cp16(sb + so + j * 16,        Ah + g + j * 8);
            cp16(sb + LA_B + so + j * 16, Al + g + j * 8);
        }
    }
    {
        const int t = tid & 127;
        const int r = t >> 1, hf = t & 1;
        const size_t g = (size_t)r * LK_ + kof + hf * 16;
        const uint32_t so = (uint32_t)r * (LPAD_ * 2) + hf * 32;
        const uint32_t base = sb + 2 * LA_B + (tid >> 7) * LB_B;
        const __nv_bfloat16* src = (tid < 128) ? Bh : Bl;
        cp16(base + so,      src + g);
        cp16(base + so + 16, src + g + 8);
    }
}

__global__ __launch_bounds__(256)
void landmark_mma_kernel(const __nv_bfloat16* __restrict__ Eh, const __nv_bfloat16* __restrict__ El,
                         const __nv_bfloat16* __restrict__ kth, const __nv_bfloat16* __restrict__ ktl,
                         const __nv_bfloat16* __restrict__ vth, const __nv_bfloat16* __restrict__ vtl,
                         float* __restrict__ klm, float* __restrict__ vlm)
{
    extern __shared__ __align__(16) char dyn[];
    const uint32_t sbase = smem_u32(dyn);

    const int bid   = blockIdx.x;
    const int which = bid & 1;
    const int bh    = bid >> 1;
    const int h     = bh & 15;

    const __nv_bfloat16* Ah = Eh + (size_t)h * KL_ * LK_;
    const __nv_bfloat16* Al = El + (size_t)h * KL_ * LK_;
    const __nv_bfloat16* Bh = (which ? vth : kth) + (size_t)bh * D_ * LK_;
    const __nv_bfloat16* Bl = (which ? vtl : ktl) + (size_t)bh * D_ * LK_;
    float* outp = (which ? vlm : klm) + (size_t)bh * KL_ * D_;

    const int tid  = threadIdx.x;
    const int warp = tid >> 5, lane = tid & 31;
    const int wm   = warp & 3;
    const int wn   = warp >> 2;
    const int gid  = lane >> 2;
    const int tig  = lane & 3;

    float acc[4][4][4];
#pragma unroll
    for (int mi = 0; mi < 4; mi++)
#pragma unroll
        for (int j = 0; j < 4; j++)
#pragma unroll
            for (int q = 0; q < 4; q++) acc[mi][j][q] = 0.f;

    lm_load_stage(sbase, Ah, Al, Bh, Bl, 0, tid);
    cp_commit();

    for (int c = 0; c < LK_ / LBK_; c++) {
        const int st = c & 1;
        if (c + 1 < LK_ / LBK_) {
            lm_load_stage(sbase + (st ^ 1) * LSTG_, Ah, Al, Bh, Bl,
                          (c + 1) * LBK_, tid);
            cp_commit();
            CP_WAIT(1);
        } else {
            CP_WAIT(0);
        }
        __syncthreads();

        const __nv_bfloat16* sA  = (const __nv_bfloat16*)(dyn + st * LSTG_);
        const __nv_bfloat16* sAl = (const __nv_bfloat16*)(dyn + st * LSTG_ + LA_B);
        const __nv_bfloat16* sB  = (const __nv_bfloat16*)(dyn + st * LSTG_ + 2 * LA_B);
        const __nv_bfloat16* sBl = (const __nv_bfloat16*)(dyn + st * LSTG_ + 2 * LA_B + LB_B);

#pragma unroll
        for (int kk = 0; kk < LBK_; kk += 16) {
            uint32_t rbh[4][2], rbl[4][2];
#pragma unroll
            for (int j = 0; j < 4; j++) {
                const int rb = wn * 32 + j * 8 + gid;
                rbh[j][0] = *(const uint32_t*)&sB [rb * LPAD_ + kk + 2 * tig];
                rbh[j][1] = *(const uint32_t*)&sB [rb * LPAD_ + kk + 2 * tig + 8];
                rbl[j][0] = *(const uint32_t*)&sBl[rb * LPAD_ + kk + 2 * tig];
                rbl[j][1] = *(const uint32_t*)&sBl[rb * LPAD_ + kk + 2 * tig + 8];
            }
            uint32_t ra[4][4];
#pragma unroll
            for (int mi = 0; mi < 4; mi++) {
                const int rr = wm * 64 + mi * 16 + gid;
                ra[mi][0] = *(const uint32_t*)&sA[rr * LPAD_ + kk + 2 * tig];
                ra[mi][1] = *(const uint32_t*)&sA[(rr + 8) * LPAD_ + kk + 2 * tig];
                ra[mi][2] = *(const uint32_t*)&sA[rr * LPAD_ + kk + 2 * tig + 8];
                ra[mi][3] = *(const uint32_t*)&sA[(rr + 8) * LPAD_ + kk + 2 * tig + 8];
            }
#pragma unroll
            for (int mi = 0; mi < 4; mi++)
#pragma unroll
                for (int j = 0; j < 4; j++)
                    MMA16816(acc[mi][j], ra[mi], rbh[j]);
#pragma unroll
            for (int mi = 0; mi < 4; mi++)
#pragma unroll
                for (int j = 0; j < 4; j++)
                    MMA16816(acc[mi][j], ra[mi], rbl[j]);
#pragma unroll
            for (int mi = 0; mi < 4; mi++) {
                const int rr = wm * 64 + mi * 16 + gid;
                ra[mi][0] = *(const uint32_t*)&sAl[rr * LPAD_ + kk + 2 * tig];
                ra[mi][1] = *(const uint32_t*)&sAl[(rr + 8) * LPAD_ + kk + 2 * tig];
                ra[mi][2] = *(const uint32_t*)&sAl[rr * LPAD_ + kk + 2 * tig + 8];
                ra[mi][3] = *(const uint32_t*)&sAl[(rr + 8) * LPAD_ + kk + 2 * tig + 8];
            }
#pragma unroll
            for (int mi = 0; mi < 4; mi++)
#pragma unroll
                for (int j = 0; j < 4; j++)
                    MMA16816(acc[mi][j], ra[mi], rbh[j]);
        }
        __syncthreads();
    }

#pragma unroll
    for (int mi = 0; mi < 4; mi++) {
        const int row = wm * 64 + mi * 16 + gid;
#pragma unroll
        for (int j = 0; j < 4; j++) {
            const int col = wn * 32 + j * 8 + 2 * tig;
            *(float2*)(outp + (size_t)row * D_ + col) =
                make_float2(acc[mi][j][0], acc[mi][j][1]);
            *(float2*)(outp + (size_t)(row + 8) * D_ + col) =
                make_float2(acc[mi][j][2], acc[mi][j][3]);
        }
    }
}

// ---------------------------------------------------------------------------
// Tensorized fused attention.
// Grid (64 bh, 2 halves), 256 threads, 1 CTA/SM.
// smem layout (bytes):
//   klmH [256][72]bf16  @0        (36864)
//   klmL                @36864    (36864)
//   vtH  [64][264]bf16  @73728    (33792)   row = d, col = landmark k
//   vtL                 @107520   (33792)
//   qH   [64][72]bf16   @141312   (9216)
//   qL                  @150528   (9216)
//   Sbuf [64][268]f32   @159744   (68608)   reused: Phi at row*536, Plo at row*536+272 (bf16 idx)
//   rec  [64]f32        @228352   (256)     total 228608
// ---------------------------------------------------------------------------
#define AKP_  72
#define AVP_  264
#define SP2_  268
#define A_KLMH 0
#define A_KLML 36864
#define A_VTH  73728
#define A_VTL  107520
#define A_QH   141312
#define A_QL   150528
#define A_SBUF 159744
#define A_REC  228352
#define ATTN_SMEM_BYTES 228608

__global__ __launch_bounds__(256)
void attn_mma_kernel(const float* __restrict__ qkv, const float* __restrict__ klm,
                     const float* __restrict__ vlm, float* __restrict__ ao)
{
    extern __shared__ __align__(16) char smb[];
    const int bh = blockIdx.x;
    const int half = blockIdx.y;
    const int b = bh >> 4, h = bh & 15;
    const int tid = threadIdx.x;
    const int warp = tid >> 5, lane = tid & 31;
    const int gid = lane >> 2, tig = lane & 3;

    __nv_bfloat16* klmH = (__nv_bfloat16*)(smb + A_KLMH);
    __nv_bfloat16* klmL = (__nv_bfloat16*)(smb + A_KLML);
    __nv_bfloat16* vtH  = (__nv_bfloat16*)(smb + A_VTH);
    __nv_bfloat16* vtL  = (__nv_bfloat16*)(smb + A_VTL);
    __nv_bfloat16* qH   = (__nv_bfloat16*)(smb + A_QH);
    __nv_bfloat16* qL   = (__nv_bfloat16*)(smb + A_QL);
    float* Sbuf = (float*)(smb + A_SBUF);
    __nv_bfloat16* PhiB = (__nv_bfloat16*)(smb + A_SBUF);   // [r*536 + c]
    __nv_bfloat16* PloB = PhiB + 272;                       // [r*536 + 272 + c]
    float* rec = (float*)(smb + A_REC);

    // ---- init: stage vlm fp32 into Sbuf [256][66]; split klm directly ----
    {
        const float* vsrc = vlm + ((size_t)bh * KL_ + tid) * D_;
        float* st = Sbuf + tid * 66;
#pragma unroll
        for (int i = 0; i < 16; i++) {
            float4 v = *(const float4*)(vsrc + i * 4);
            st[i * 4 + 0] = v.x; st[i * 4 + 1] = v.y;
            st[i * 4 + 2] = v.z; st[i * 4 + 3] = v.w;
        }
        const float* ksrc = klm + ((size_t)bh * KL_ + tid) * D_;
        __nv_bfloat16* kh = klmH + tid * AKP_;
        __nv_bfloat16* kl = klmL + tid * AKP_;
#pragma unroll
        for (int i = 0; i < 16; i++) {
            float4 v = *(const float4*)(ksrc + i * 4);
            float f[4] = {v.x, v.y, v.z, v.w};
#pragma unroll
            for (int q = 0; q < 4; q++) {
                __nv_bfloat16 hi = __float2bfloat16(f[q]);
                kh[i * 4 + q] = hi;
                kl[i * 4 + q] = __float2bfloat16(f[q] - __bfloat162float(hi));
            }
        }
    }
    __syncthreads();
    // transpose-split vlm: vtH/vtL[d][k]
    {
        const int d = tid & 63, kb = (tid >> 6) * 64;
        for (int i = 0; i < 64; i++) {
            const int k = kb + i;
            float f = Sbuf[k * 66 + d];
            __nv_bfloat16 hi = __float2bfloat16(f);
            vtH[d * AVP_ + k] = hi;
            vtL[d * AVP_ + k] = __float2bfloat16(f - __bfloat162float(hi));
        }
    }
    __syncthreads();

    const int base = half * 2048;
    for (int tile = 0; tile < 32; tile++) {
        const int t0 = base + tile * 64;

        // ---- load q tile, pre-scaled, split ----
        {
            const int r = tid >> 2, ds = (tid & 3) * 16;
            const float* qs = qkv + ((size_t)(b * N_ + t0 + r)) * C3_ + h * D_ + ds;
            __nv_bfloat16* qhp = qH + r * AKP_ + ds;
            __nv_bfloat16* qlp = qL + r * AKP_ + ds;
#pragma unroll
            for (int i = 0; i < 4; i++) {
                float4 v = *(const float4*)(qs + i * 4);
                float f[4] = {v.x * 0.125f, v.y * 0.125f, v.z * 0.125f, v.w * 0.125f};
#pragma unroll
                for (int q = 0; q < 4; q++) {
                    __nv_bfloat16 hi = __float2bfloat16(f[q]);
                    qhp[i * 4 + q] = hi;
                    qlp[i * 4 + q] = __float2bfloat16(f[q] - __bfloat162float(hi));
                }
            }
        }
        __syncthreads();

        // ---- S-GEMM: warp tile 32x64 over [64][256], K=64 ----
        {
            const int wm = warp & 1, wn = warp >> 1;
            float acc[2][8][4];
#pragma unroll
            for (int mi = 0; mi < 2; mi++)
#pragma unroll
                for (int j = 0; j < 8; j++)
#pragma unroll
                    for (int q = 0; q < 4; q++) acc[mi][j][q] = 0.f;

#pragma unroll
            for (int kk = 0; kk < 64; kk += 16) {
                uint32_t rbh[8][2], rbl[8][2];
#pragma unroll
                for (int j = 0; j < 8; j++) {
                    const int rb = wn * 64 + j * 8 + gid;
                    rbh[j][0] = *(const uint32_t*)&klmH[rb * AKP_ + kk + 2 * tig];
                    rbh[j][1] = *(const uint32_t*)&klmH[rb * AKP_ + kk + 2 * tig + 8];
                    rbl[j][0] = *(const uint32_t*)&klmL[rb * AKP_ + kk + 2 * tig];
                    rbl[j][1] = *(const uint32_t*)&klmL[rb * AKP_ + kk + 2 * tig + 8];
                }
                uint32_t ra[2][4];
#pragma unroll
                for (int mi = 0; mi < 2; mi++) {
                    const int rr = wm * 32 + mi * 16 + gid;
                    ra[mi][0] = *(const uint32_t*)&qH[rr * AKP_ + kk + 2 * tig];
                    ra[mi][1] = *(const uint32_t*)&qH[(rr + 8) * AKP_ + kk + 2 * tig];
                    ra[mi][2] = *(const uint32_t*)&qH[rr * AKP_ + kk + 2 * tig + 8];
                    ra[mi][3] = *(const uint32_t*)&qH[(rr + 8) * AKP_ + kk + 2 * tig + 8];
                }
#pragma unroll
                for (int mi = 0; mi < 2; mi++)
#pragma unroll
                    for (int j = 0; j < 8; j++) {
                        MMA16816(acc[mi][j], ra[mi], rbh[j]);
                        MMA16816(acc[mi][j], ra[mi], rbl[j]);
                    }
#pragma unroll
                for (int mi = 0; mi < 2; mi++) {
                    const int rr = wm * 32 + mi * 16 + gid;
                    ra[mi][0] = *(const uint32_t*)&qL[rr * AKP_ + kk + 2 * tig];
                    ra[mi][1] = *(const uint32_t*)&qL[(rr + 8) * AKP_ + kk + 2 * tig];
                    ra[mi][2] = *(const uint32_t*)&qL[rr * AKP_ + kk + 2 * tig + 8];
                    ra[mi][3] = *(const uint32_t*)&qL[(rr + 8) * AKP_ + kk + 2 * tig + 8];
                }
#pragma unroll
                for (int mi = 0; mi < 2; mi++)
#pragma unroll
                    for (int j = 0; j < 8; j++)
                        MMA16816(acc[mi][j], ra[mi], rbh[j]);
            }
#pragma unroll
            for (int mi = 0; mi < 2; mi++) {
                const int r = wm * 32 + mi * 16 + gid;
#pragma unroll
                for (int j = 0; j < 8; j++) {
                    const int c = wn * 64 + j * 8 + 2 * tig;
                    *(float2*)&Sbuf[r * SP2_ + c] =
                        make_float2(acc[mi][j][0], acc[mi][j][1]);
                    *(float2*)&Sbuf[(r + 8) * SP2_ + c] =
                        make_float2(acc[mi][j][2], acc[mi][j][3]);
                }
            }
        }
        __syncthreads();

        // ---- softmax + in-place P hi/lo conversion (rows warp*8..+7) ----
#pragma unroll 1
        for (int i = 0; i < 8; i++) {
            const int r = warp * 8 + i;
            float v[8];
#pragma unroll
            for (int jj = 0; jj < 8; jj++)
                v[jj] = Sbuf[r * SP2_ + lane + 32 * jj];
            float m = v[0];
#pragma unroll
            for (int jj = 1; jj < 8; jj++) m = fmaxf(m, v[jj]);
#pragma unroll
            for (int off = 16; off > 0; off >>= 1)
                m = fmaxf(m, __shfl_xor_sync(0xffffffffu, m, off));
            float s = 0.f;
#pragma unroll
            for (int jj = 0; jj < 8; jj++) { v[jj] = __expf(v[jj] - m); s += v[jj]; }
#pragma unroll
            for (int off = 16; off > 0; off >>= 1)
                s += __shfl_xor_sync(0xffffffffu, s, off);
            __syncwarp();
#pragma unroll
            for (int jj = 0; jj < 8; jj++) {
                const int c = lane + 32 * jj;
                __nv_bfloat16 hi = __float2bfloat16(v[jj]);
                PhiB[r * 536 + c] = hi;
                PloB[r * 536 + c] = __float2bfloat16(v[jj] - __bfloat162float(hi));
            }
            if (lane == 0) rec[r] = 1.f / s;
        }
        __syncthreads();

        // ---- O-GEMM: warp tile 16x32 over [64][64], K=256 ----
        {
            const int wm = warp & 3, wn = warp >> 2;
            float acc[4][4];
#pragma unroll
            for (int j = 0; j < 4; j++)
#pragma unroll
                for (int q = 0; q < 4; q++) acc[j][q] = 0.f;

            const int pr = wm * 16 + gid;
#pragma unroll 4
            for (int kk = 0; kk < 256; kk += 16) {
                uint32_t rbh[4][2], rbl[4][2];
#pragma unroll
                for (int j = 0; j < 4; j++) {
                    const int rb = wn * 32 + j * 8 + gid;
                    rbh[j][0] = *(const uint32_t*)&vtH[rb * AVP_ + kk + 2 * tig];
                    rbh[j][1] = *(const uint32_t*)&vtH[rb * AVP_ + kk + 2 * tig + 8];
                    rbl[j][0] = *(const uint32_t*)&vtL[rb * AVP_ + kk + 2 * tig];
                    rbl[j][1] = *(const uint32_t*)&vtL[rb * AVP_ + kk + 2 * tig + 8];
                }
                uint32_t ra[4];
                ra[0] = *(const uint32_t*)&PhiB[pr * 536 + kk + 2 * tig];
                ra[1] = *(const uint32_t*)&PhiB[(pr + 8) * 536 + kk + 2 * tig];
                ra[2] = *(const uint32_t*)&PhiB[pr * 536 + kk + 2 * tig + 8];
                ra[3] = *(const uint32_t*)&PhiB[(pr + 8) * 536 + kk + 2 * tig + 8];
#pragma unroll
                for (int j = 0; j < 4; j++) MMA16816(acc[j], ra, rbh[j]);
#pragma unroll
                for (int j = 0; j < 4; j++) MMA16816(acc[j], ra, rbl[j]);
                ra[0] = *(const uint32_t*)&PloB[pr * 536 + kk + 2 * tig];
                ra[1] = *(const uint32_t*)&PloB[(pr + 8) * 536 + kk + 2 * tig];
                ra[2] = *(const uint32_t*)&PloB[pr * 536 + kk + 2 * tig + 8];
                ra[3] = *(const uint32_t*)&PloB[(pr + 8) * 536 + kk + 2 * tig + 8];
#pragma unroll
                for (int j = 0; j < 4; j++) MMA16816(acc[j], ra, rbh[j]);
            }
            const float rc0 = rec[pr], rc1 = rec[pr + 8];
            float* ob = ao + ((size_t)bh * N_ + t0) * D_;
#pragma unroll
            for (int j = 0; j < 4; j++) {
                const int c = wn * 32 + j * 8 + 2 * tig;
                *(float2*)&ob[(size_t)pr * D_ + c] =
                    make_float2(acc[j][0] * rc0, acc[j][1] * rc0);
                *(float2*)&ob[(size_t)(pr + 8) * D_ + c] =
                    make_float2(acc[j][2] * rc1, acc[j][3] * rc1);
            }
        }
        __syncthreads();
    }
}

// ---------------------------------------------------------------------------
extern "C" void kernel_launch(void* const* d_in, const int* in_sizes, int n_in,
                              void* d_out, int out_size)
{
    (void)in_sizes; (void)n_in; (void)out_size;
    const float* x     = (const float*)d_in[0];
    const float* Wqkv  = (const float*)d_in[1];
    const float* E     = (const float*)d_in[2];
    const float* Wproj = (const float*)d_in[3];
    const float* bproj = (const float*)d_in[4];
    float* out = (float*)d_out;

    void *p_qkv, *p_klm, *p_vlm, *p_ao;
    void *p_xh, *p_xl, *p_w3h, *p_w3l, *p_aoh, *p_aol, *p_wph, *p_wpl;
    void *p_eh, *p_el, *p_kth, *p_ktl, *p_vth, *p_vtl;
    cudaGetSymbolAddress(&p_qkv, g_qkv);
    cudaGetSymbolAddress(&p_klm, g_klm);
    cudaGetSymbolAddress(&p_vlm, g_vlm);
    cudaGetSymbolAddress(&p_ao,  g_ao);
    cudaGetSymbolAddress(&p_xh,  g_xh);
    cudaGetSymbolAddress(&p_xl,  g_xl);
    cudaGetSymbolAddress(&p_w3h, g_w3h);
    cudaGetSymbolAddress(&p_w3l, g_w3l);
    cudaGetSymbolAddress(&p_aoh, g_aoh);
    cudaGetSymbolAddress(&p_aol, g_aol);
    cudaGetSymbolAddress(&p_wph, g_wph);
    cudaGetSymbolAddress(&p_wpl, g_wpl);
    cudaGetSymbolAddress(&p_eh,  g_eh);
    cudaGetSymbolAddress(&p_el,  g_el);
    cudaGetSymbolAddress(&p_kth, g_kth);
    cudaGetSymbolAddress(&p_ktl, g_ktl);
    cudaGetSymbolAddress(&p_vth, g_vth);
    cudaGetSymbolAddress(&p_vtl, g_vtl);

    float* qkv = (float*)p_qkv;
    float* klm = (float*)p_klm;
    float* vlm = (float*)p_vlm;
    float* ao  = (float*)p_ao;

    cudaFuncSetAttribute(attn_mma_kernel, cudaFuncAttributeMaxDynamicSharedMemorySize,
                         ATTN_SMEM_BYTES);
    cudaFuncSetAttribute(gemm_mma_kernel, cudaFuncAttributeMaxDynamicSharedMemorySize,
                         GSMEM);
    cudaFuncSetAttribute(landmark_mma_kernel, cudaFuncAttributeMaxDynamicSharedMemorySize,
                         LSMEM);

    const int XN  = B_ * N_ * C_;
    const int W3N = C3_ * C_;
    const int WPN = C_ * C_;
    const int EN  = H_ * KL_ * N_;

    split_kernel<<<(XN / 4 + 255) / 256, 256>>>(x, (__nv_bfloat16*)p_xh,
                                                (__nv_bfloat16*)p_xl, XN / 4);
    split_kernel<<<(W3N / 4 + 255) / 256, 256>>>(Wqkv, (__nv_bfloat16*)p_w3h,
                                                 (__nv_bfloat16*)p_w3l, W3N / 4);
    split_kernel<<<(EN / 4 + 255) / 256, 256>>>(E, (__nv_bfloat16*)p_eh,
                                                (__nv_bfloat16*)p_el, EN / 4);

    // 1) qkv = x @ Wqkv^T
    gemm_mma_kernel<<<dim3(C3_ / 128, (B_ * N_) / 128), 256, GSMEM>>>(
        (__nv_bfloat16*)p_xh, (__nv_bfloat16*)p_xl,
        (__nv_bfloat16*)p_w3h, (__nv_bfloat16*)p_w3l, qkv, nullptr, C3_);

    // 2) K/V transpose-split
    kvsplit_kernel<<<64 * 64 * 2, 256>>>(qkv,
        (__nv_bfloat16*)p_kth, (__nv_bfloat16*)p_ktl,
        (__nv_bfloat16*)p_vth, (__nv_bfloat16*)p_vtl);

    // 3) landmark projections via MMA
    landmark_mma_kernel<<<128, 256, LSMEM>>>(
        (__nv_bfloat16*)p_eh, (__nv_bfloat16*)p_el,
        (__nv_bfloat16*)p_kth, (__nv_bfloat16*)p_ktl,
        (__nv_bfloat16*)p_vth, (__nv_bfloat16*)p_vtl, klm, vlm);

    // 4) tensorized fused attention
    attn_mma_kernel<<<dim3(64, 2), 256, ATTN_SMEM_BYTES>>>(qkv, klm, vlm, ao);

    split_kernel<<<(XN / 4 + 255) / 256, 256>>>(ao, (__nv_bfloat16*)p_aoh,
                                                (__nv_bfloat16*)p_aol, XN / 4);
    split_kernel<<<(WPN / 4 + 255) / 256, 256>>>(Wproj, (__nv_bfloat16*)p_wph,
                                                 (__nv_bfloat16*)p_wpl, WPN / 4);

    // 5) out = ao @ Wproj^T + bproj
    gemm_mma_kernel<<<dim3(C_ / 128, (B_ * N_) / 128), 256, GSMEM>>>(
        (__nv_bfloat16*)p_aoh, (__nv_bfloat16*)p_aol,
        (__nv_bfloat16*)p_wph, (__nv_bfloat16*)p_wpl, out, bproj, C_);
}